// round 1
// baseline (speedup 1.0000x reference)
#include <cuda_runtime.h>
#include <cmath>

// Problem constants (fixed by setup_inputs: B=8, L=20*50+1, d_model=1024, H=16, 2 layers)
namespace {
constexpr int B   = 8;
constexpr int L   = 1001;
constexpr int D   = 1024;
constexpr int H   = 16;
constexpr int DK  = 64;    // d_model / nhead
constexpr int NKQ = 1000;  // N*K (query row index)
constexpr int KCLS = 50;   // K (class block size)
constexpr int TI  = 64;    // query-row tile
constexpr int TJ  = 64;    // key tile
constexpr int NT  = (L + TJ - 1) / TJ;  // 16 tiles
constexpr int LDQ = TI + 1;             // smem pad (stride 65 -> 2-way max conflicts)
constexpr float SCALE = 0.125f;         // 1/sqrt(64)
constexpr int SMEM_FLOATS = 2 * DK * LDQ + TI * TJ;  // Qt + Kt + P = 49664 B
}

// Layer-1 intermediate activations (32.8 MB). Static __device__ scratch is the
// sanctioned workaround for the no-allocation rule.
__device__ float g_x1[(size_t)B * L * D];

// One fused attention layer (flash-style, online softmax with post-softmax
// structured multiplier folded into the numerator).
// grid: (NT row-tiles, B*H). block: 256 threads = 16x16, each owns a 4x4
// micro-tile of the 64x64 S tile AND of the 64x64 (rows x dk) O tile.
__global__ void __launch_bounds__(256)
encoder_layer_kernel(const float* __restrict__ x,
                     const float* __restrict__ w6,   // [H][6] for this layer
                     float* __restrict__ y)
{
    extern __shared__ float sm[];
    float* Qt = sm;                  // [DK][LDQ], Qt[k][row], pre-scaled by 1/8
    float* Kt = sm + DK * LDQ;       // [DK][LDQ], Kt[k][j] (also serves as V)
    float* Pm = sm + 2 * DK * LDQ;   // [TI][TJ], multiplier-weighted exp

    const int t  = threadIdx.x;
    const int tr = t >> 4;           // 0..15 (row group)
    const int tc = t & 15;           // 0..15 (col group); 16 tc lanes = half-warp
    const int r0 = tr * 4;
    const int c0 = tc * 4;
    const int h  = blockIdx.y & (H - 1);
    const int b  = blockIdx.y >> 4;
    const int i_base = blockIdx.x * TI;

    // 6 tanh'd class weights for this head
    float t6[6];
#pragma unroll
    for (int q = 0; q < 6; ++q) t6[q] = tanhf(w6[h * 6 + q]);

    const float* xb = x + (size_t)b * L * D + h * DK;
    float*       yb = y + (size_t)b * L * D + h * DK;

    // ---- load Q tile, transposed + pre-scaled ----
    for (int idx = t; idx < TI * 16; idx += 256) {
        int row = idx >> 4, k4 = idx & 15;
        int gi = i_base + row;
        float4 v = make_float4(0.f, 0.f, 0.f, 0.f);
        if (gi < L) v = *reinterpret_cast<const float4*>(xb + (size_t)gi * D + k4 * 4);
        Qt[(k4 * 4 + 0) * LDQ + row] = v.x * SCALE;
        Qt[(k4 * 4 + 1) * LDQ + row] = v.y * SCALE;
        Qt[(k4 * 4 + 2) * LDQ + row] = v.z * SCALE;
        Qt[(k4 * 4 + 3) * LDQ + row] = v.w * SCALE;
    }

    // online-softmax state (per owned row) + O accumulator (4 rows x 4 dk)
    float m[4], l[4], o[4][4];
#pragma unroll
    for (int u = 0; u < 4; ++u) {
        m[u] = -INFINITY; l[u] = 0.f;
#pragma unroll
        for (int v = 0; v < 4; ++v) o[u][v] = 0.f;
    }

    int ib[4]; bool iq[4];
#pragma unroll
    for (int u = 0; u < 4; ++u) {
        int gi = i_base + r0 + u;
        ib[u] = gi / KCLS;
        iq[u] = (gi == NKQ);
    }

    for (int jt = 0; jt < NT; ++jt) {
        const int j_base = jt * TJ;
        __syncthreads();   // protect Kt/Pm from previous iteration's O-gemm
        // ---- load K(=V) tile, transposed ----
        for (int idx = t; idx < TJ * 16; idx += 256) {
            int row = idx >> 4, k4 = idx & 15;
            int gj = j_base + row;
            float4 v = make_float4(0.f, 0.f, 0.f, 0.f);
            if (gj < L) v = *reinterpret_cast<const float4*>(xb + (size_t)gj * D + k4 * 4);
            Kt[(k4 * 4 + 0) * LDQ + row] = v.x;
            Kt[(k4 * 4 + 1) * LDQ + row] = v.y;
            Kt[(k4 * 4 + 2) * LDQ + row] = v.z;
            Kt[(k4 * 4 + 3) * LDQ + row] = v.w;
        }
        __syncthreads();

        // ---- S = (Q*scale) K^T, 4x4 per thread ----
        float acc[4][4];
#pragma unroll
        for (int u = 0; u < 4; ++u)
#pragma unroll
            for (int v = 0; v < 4; ++v) acc[u][v] = 0.f;

#pragma unroll 8
        for (int k = 0; k < DK; ++k) {
            float qa[4], kb[4];
#pragma unroll
            for (int u = 0; u < 4; ++u) qa[u] = Qt[k * LDQ + r0 + u];
#pragma unroll
            for (int v = 0; v < 4; ++v) kb[v] = Kt[k * LDQ + c0 + v];
#pragma unroll
            for (int u = 0; u < 4; ++u)
#pragma unroll
                for (int v = 0; v < 4; ++v) acc[u][v] += qa[u] * kb[v];
        }

        // ---- per-tile column metadata ----
        int jb[4]; bool jvalid[4], jq[4];
#pragma unroll
        for (int v = 0; v < 4; ++v) {
            int gj = j_base + c0 + v;
            jb[v] = gj / KCLS;
            jvalid[v] = (gj < L);
            jq[v] = (gj == NKQ);
        }

        // ---- online softmax + structured multiplier ----
#pragma unroll
        for (int u = 0; u < 4; ++u) {
            float s[4];
#pragma unroll
            for (int v = 0; v < 4; ++v)
                s[v] = jvalid[v] ? acc[u][v] : -INFINITY;
            float rm = fmaxf(fmaxf(s[0], s[1]), fmaxf(s[2], s[3]));
#pragma unroll
            for (int off = 8; off > 0; off >>= 1)
                rm = fmaxf(rm, __shfl_xor_sync(0xffffffffu, rm, off));
            float mn = fmaxf(m[u], rm);
            float sc = __expf(m[u] - mn);   // exp(-inf)=0 on first tile
            l[u] *= sc;
#pragma unroll
            for (int v = 0; v < 4; ++v) o[u][v] *= sc;
            float ps = 0.f;
            const int gi = i_base + r0 + u;
#pragma unroll
            for (int v = 0; v < 4; ++v) {
                float e = jvalid[v] ? __expf(s[v] - mn) : 0.f;
                ps += e;                    // denominator uses raw exp
                const int gj = j_base + c0 + v;
                float tm;
                if (iq[u])          tm = jq[v] ? t6[5] : t6[4];
                else if (jq[v])     tm = t6[3];
                else if (gi == gj)  tm = t6[0];
                else                tm = (ib[u] == jb[v]) ? t6[1] : t6[2];
                Pm[(r0 + u) * TJ + c0 + v] = tm * e;   // numerator weighted
            }
#pragma unroll
            for (int off = 8; off > 0; off >>= 1)
                ps += __shfl_xor_sync(0xffffffffu, ps, off);
            l[u] += ps;
            m[u] = mn;
        }
        __syncthreads();

        // ---- O += P' @ V (V tile == K tile data) ----
#pragma unroll 8
        for (int jj = 0; jj < TJ; ++jj) {
            float pv[4], vv[4];
#pragma unroll
            for (int u = 0; u < 4; ++u) pv[u] = Pm[(r0 + u) * TJ + jj];
#pragma unroll
            for (int v = 0; v < 4; ++v) vv[v] = Kt[(c0 + v) * LDQ + jj];
#pragma unroll
            for (int u = 0; u < 4; ++u)
#pragma unroll
                for (int v = 0; v < 4; ++v) o[u][v] += pv[u] * vv[v];
        }
    }

    // ---- finalize: divide by denominator, write back (coalesced float4) ----
#pragma unroll
    for (int u = 0; u < 4; ++u) {
        int gi = i_base + r0 + u;
        if (gi < L) {
            float inv = 1.0f / l[u];
            float4 r;
            r.x = o[u][0] * inv; r.y = o[u][1] * inv;
            r.z = o[u][2] * inv; r.w = o[u][3] * inv;
            *reinterpret_cast<float4*>(yb + (size_t)gi * D + c0) = r;
        }
    }
}

extern "C" void kernel_launch(void* const* d_in, const int* in_sizes, int n_in,
                              void* d_out, int out_size)
{
    const float* samples = (const float*)d_in[0];          // [B, L, D] fp32
    const float* weights = (const float*)d_in[1];          // [2, H, 6] fp32
    float* out = (float*)d_out;                            // [B, L, D] fp32

    float* scratch = nullptr;
    cudaGetSymbolAddress((void**)&scratch, g_x1);          // host query, capture-safe

    const size_t smem = SMEM_FLOATS * sizeof(float);       // 49664 B > 48K -> opt-in
    cudaFuncSetAttribute(encoder_layer_kernel,
                         cudaFuncAttributeMaxDynamicSharedMemorySize, (int)smem);

    dim3 grid(NT, B * H);   // 16 x 128
    encoder_layer_kernel<<<grid, 256, smem>>>(samples, weights, scratch);
    encoder_layer_kernel<<<grid, 256, smem>>>(scratch, weights + H * 6, out);
}

// round 2
// speedup vs baseline: 3.1068x; 3.1068x over previous
#include <cuda_runtime.h>
#include <cuda_bf16.h>
#include <cmath>
#include <cstdint>

// Problem constants (fixed by setup_inputs: B=8, L=20*50+1, d_model=1024, H=16, 2 layers)
namespace {
constexpr int B    = 8;
constexpr int L    = 1001;
constexpr int D    = 1024;
constexpr int H    = 16;
constexpr int DK   = 64;
constexpr int NKQ  = 1000;   // query row index
constexpr int KCLS = 50;     // class block size
constexpr int TI   = 64;     // row tile (4 warps x 16)
constexpr int TJ   = 64;     // key tile
constexpr int NT   = (L + TJ - 1) / TJ;   // 16
constexpr int LDS  = 72;     // bf16 elems per smem row (stride 144B: conflict-free ldmatrix)
constexpr float SCALE = 0.125f;
}

// Layer-1 intermediate (32.8 MB) — __device__ global scratch (no-alloc rule).
__device__ float g_x1[(size_t)B * L * D];

__device__ __forceinline__ uint32_t smem_u32(const void* p) {
    return (uint32_t)__cvta_generic_to_shared(p);
}
__device__ __forceinline__ void ldmx4(uint32_t a, uint32_t& r0, uint32_t& r1, uint32_t& r2, uint32_t& r3) {
    asm volatile("ldmatrix.sync.aligned.m8n8.x4.shared.b16 {%0,%1,%2,%3},[%4];"
                 : "=r"(r0), "=r"(r1), "=r"(r2), "=r"(r3) : "r"(a));
}
__device__ __forceinline__ void ldmx4t(uint32_t a, uint32_t& r0, uint32_t& r1, uint32_t& r2, uint32_t& r3) {
    asm volatile("ldmatrix.sync.aligned.m8n8.x4.trans.shared.b16 {%0,%1,%2,%3},[%4];"
                 : "=r"(r0), "=r"(r1), "=r"(r2), "=r"(r3) : "r"(a));
}
__device__ __forceinline__ void mma_bf16(float* d, const uint32_t* a, uint32_t b0, uint32_t b1) {
    asm volatile("mma.sync.aligned.m16n8k16.row.col.f32.bf16.bf16.f32 "
                 "{%0,%1,%2,%3},{%4,%5,%6,%7},{%8,%9},{%0,%1,%2,%3};"
                 : "+f"(d[0]), "+f"(d[1]), "+f"(d[2]), "+f"(d[3])
                 : "r"(a[0]), "r"(a[1]), "r"(a[2]), "r"(a[3]), "r"(b0), "r"(b1));
}
__device__ __forceinline__ uint32_t pack_bf2(__nv_bfloat16 lo, __nv_bfloat16 hi) {
    __nv_bfloat162 t = __halves2bfloat162(lo, hi);   // lo -> .x (low half)
    return *reinterpret_cast<uint32_t*>(&t);
}
// split a,b into bf16 hi-pair and lo-pair (packed, low half = first arg)
__device__ __forceinline__ void split2(float a, float b, uint32_t& hi, uint32_t& lo) {
    __nv_bfloat16 ha = __float2bfloat16_rn(a), hb = __float2bfloat16_rn(b);
    float ra = a - __bfloat162float(ha);
    float rb = b - __bfloat162float(hb);
    hi = pack_bf2(ha, hb);
    lo = pack_bf2(__float2bfloat16_rn(ra), __float2bfloat16_rn(rb));
}

// Stage a 64x64 fp32 tile (rows base..base+63 of x-slice, cols = this head's dk)
// into bf16 hi/lo smem tiles, zero-filling out-of-range rows. 128 threads.
__device__ __forceinline__ void stage_tile(const float* __restrict__ src, int base_row,
                                           float scale, __nv_bfloat16* sH, __nv_bfloat16* sL,
                                           int tid) {
#pragma unroll
    for (int it = 0; it < 8; ++it) {
        int idx = tid + 128 * it;
        int row = idx >> 4, c4 = (idx & 15) * 4;
        int g = base_row + row;
        float4 v = make_float4(0.f, 0.f, 0.f, 0.f);
        if (g < L) v = *reinterpret_cast<const float4*>(src + (size_t)g * D + c4);
        v.x *= scale; v.y *= scale; v.z *= scale; v.w *= scale;
        uint32_t h0, l0, h1, l1;
        split2(v.x, v.y, h0, l0);
        split2(v.z, v.w, h1, l1);
        uint32_t* pH = reinterpret_cast<uint32_t*>(sH + row * LDS + c4);
        uint32_t* pL = reinterpret_cast<uint32_t*>(sL + row * LDS + c4);
        pH[0] = h0; pH[1] = h1;
        pL[0] = l0; pL[1] = l1;
    }
}

__device__ __forceinline__ float tmul(int gi, int ib, bool iq, int gj, const float* t6) {
    if (iq)        return (gj == NKQ) ? t6[5] : t6[4];
    if (gj == NKQ) return t6[3];
    if (gi == gj)  return t6[0];
    return (ib == gj / KCLS) ? t6[1] : t6[2];
}

__global__ void __launch_bounds__(128, 3)
encoder_layer_tc(const float* __restrict__ x,
                 const float* __restrict__ w6,   // [H][6] for this layer
                 float* __restrict__ y)
{
    __shared__ __nv_bfloat16 sKh[TJ * LDS];
    __shared__ __nv_bfloat16 sKl[TJ * LDS];

    const int tid  = threadIdx.x;
    const int w    = tid >> 5;
    const int lane = tid & 31;
    const int h    = blockIdx.y & (H - 1);
    const int b    = blockIdx.y >> 4;
    const int i_base = blockIdx.x * TI;

    const float* xb = x + (size_t)b * L * D + h * DK;
    float*       yb = y + (size_t)b * L * D + h * DK;

    float t6[6];
#pragma unroll
    for (int q = 0; q < 6; ++q) t6[q] = tanhf(w6[h * 6 + q]);

    // lane-derived ldmatrix offset pieces
    const int lrA = (lane & 7) + ((lane >> 3) & 1) * 8;  // A / trans-B row part
    const int lcA = ((lane >> 4) & 1) * 8;               // A / trans-B col part
    const int lrK = (lane & 7) + ((lane >> 4) & 1) * 8;  // non-trans B row part
    const int lcK = ((lane >> 3) & 1) * 8;               // non-trans B col part

    // ---- stage Q (pre-scaled), hoist A-fragments into registers ----
    stage_tile(xb, i_base, SCALE, sKh, sKl, tid);
    __syncthreads();
    uint32_t qh[4][4], ql[4][4];
#pragma unroll
    for (int kc = 0; kc < 4; ++kc) {
        const int off = (w * 16 + lrA) * LDS + kc * 16 + lcA;
        ldmx4(smem_u32(sKh + off), qh[kc][0], qh[kc][1], qh[kc][2], qh[kc][3]);
        ldmx4(smem_u32(sKl + off), ql[kc][0], ql[kc][1], ql[kc][2], ql[kc][3]);
    }

    float o[8][4];
#pragma unroll
    for (int nt = 0; nt < 8; ++nt)
#pragma unroll
        for (int v = 0; v < 4; ++v) o[nt][v] = 0.f;
    float m0 = -INFINITY, m1 = -INFINITY, l0 = 0.f, l1 = 0.f;

    const int gi0 = i_base + w * 16 + (lane >> 2);
    const int gi1 = gi0 + 8;
    const int ib0 = gi0 / KCLS, ib1 = gi1 / KCLS;
    const bool iq0 = (gi0 == NKQ), iq1 = (gi1 == NKQ);

    for (int jt = 0; jt < NT; ++jt) {
        const int j_base = jt * TJ;
        __syncthreads();                       // previous O-gemm reads done
        stage_tile(xb, j_base, 1.0f, sKh, sKl, tid);
        __syncthreads();

        // ---- S = Q K^T (bf16x3) ----
        float acc[8][4];
#pragma unroll
        for (int nt = 0; nt < 8; ++nt)
#pragma unroll
            for (int v = 0; v < 4; ++v) acc[nt][v] = 0.f;

#pragma unroll
        for (int kc = 0; kc < 4; ++kc) {
#pragma unroll
            for (int ntp = 0; ntp < 4; ++ntp) {
                const int off = (16 * ntp + lrK) * LDS + kc * 16 + lcK;
                uint32_t bh0, bh1, bh2, bh3, bl0, bl1, bl2, bl3;
                ldmx4(smem_u32(sKh + off), bh0, bh1, bh2, bh3);
                ldmx4(smem_u32(sKl + off), bl0, bl1, bl2, bl3);
                mma_bf16(acc[2 * ntp],     qh[kc], bh0, bh1);
                mma_bf16(acc[2 * ntp],     qh[kc], bl0, bl1);
                mma_bf16(acc[2 * ntp],     ql[kc], bh0, bh1);
                mma_bf16(acc[2 * ntp + 1], qh[kc], bh2, bh3);
                mma_bf16(acc[2 * ntp + 1], qh[kc], bl2, bl3);
                mma_bf16(acc[2 * ntp + 1], ql[kc], bh2, bh3);
            }
        }

        // ---- online softmax + structured multiplier, pack P as A-fragments ----
        float rm0 = -INFINITY, rm1 = -INFINITY;
#pragma unroll
        for (int nt = 0; nt < 8; ++nt) {
            rm0 = fmaxf(rm0, fmaxf(acc[nt][0], acc[nt][1]));
            rm1 = fmaxf(rm1, fmaxf(acc[nt][2], acc[nt][3]));
        }
        rm0 = fmaxf(rm0, __shfl_xor_sync(0xffffffffu, rm0, 1));
        rm0 = fmaxf(rm0, __shfl_xor_sync(0xffffffffu, rm0, 2));
        rm1 = fmaxf(rm1, __shfl_xor_sync(0xffffffffu, rm1, 1));
        rm1 = fmaxf(rm1, __shfl_xor_sync(0xffffffffu, rm1, 2));
        const float mn0 = fmaxf(m0, rm0), mn1 = fmaxf(m1, rm1);
        const float sc0 = __expf(m0 - mn0), sc1 = __expf(m1 - mn1);
        m0 = mn0; m1 = mn1;
        l0 *= sc0; l1 *= sc1;
#pragma unroll
        for (int nt = 0; nt < 8; ++nt) {
            o[nt][0] *= sc0; o[nt][1] *= sc0;
            o[nt][2] *= sc1; o[nt][3] *= sc1;
        }

        uint32_t ah[4][4], al[4][4];
        float ps0 = 0.f, ps1 = 0.f;
#pragma unroll
        for (int nt = 0; nt < 8; ++nt) {
            const int gj0 = j_base + nt * 8 + (lane & 3) * 2;
            const int gj1 = gj0 + 1;
            const float e00 = (gj0 < L) ? __expf(acc[nt][0] - mn0) : 0.f;
            const float e01 = (gj1 < L) ? __expf(acc[nt][1] - mn0) : 0.f;
            const float e10 = (gj0 < L) ? __expf(acc[nt][2] - mn1) : 0.f;
            const float e11 = (gj1 < L) ? __expf(acc[nt][3] - mn1) : 0.f;
            ps0 += e00 + e01;
            ps1 += e10 + e11;
            const float p00 = e00 * tmul(gi0, ib0, iq0, gj0, t6);
            const float p01 = e01 * tmul(gi0, ib0, iq0, gj1, t6);
            const float p10 = e10 * tmul(gi1, ib1, iq1, gj0, t6);
            const float p11 = e11 * tmul(gi1, ib1, iq1, gj1, t6);
            const int kc = nt >> 1, of = (nt & 1) * 2;
            split2(p00, p01, ah[kc][of],     al[kc][of]);
            split2(p10, p11, ah[kc][of + 1], al[kc][of + 1]);
        }
        ps0 += __shfl_xor_sync(0xffffffffu, ps0, 1);
        ps0 += __shfl_xor_sync(0xffffffffu, ps0, 2);
        ps1 += __shfl_xor_sync(0xffffffffu, ps1, 1);
        ps1 += __shfl_xor_sync(0xffffffffu, ps1, 2);
        l0 += ps0; l1 += ps1;

        // ---- O += P V (V tile == K tile data, trans ldmatrix) ----
#pragma unroll
        for (int kc = 0; kc < 4; ++kc) {
#pragma unroll
            for (int ntp = 0; ntp < 4; ++ntp) {
                const int off = (kc * 16 + lrA) * LDS + 16 * ntp + lcA;
                uint32_t vh0, vh1, vh2, vh3, vl0, vl1, vl2, vl3;
                ldmx4t(smem_u32(sKh + off), vh0, vh1, vh2, vh3);
                ldmx4t(smem_u32(sKl + off), vl0, vl1, vl2, vl3);
                mma_bf16(o[2 * ntp],     ah[kc], vh0, vh1);
                mma_bf16(o[2 * ntp],     ah[kc], vl0, vl1);
                mma_bf16(o[2 * ntp],     al[kc], vh0, vh1);
                mma_bf16(o[2 * ntp + 1], ah[kc], vh2, vh3);
                mma_bf16(o[2 * ntp + 1], ah[kc], vl2, vl3);
                mma_bf16(o[2 * ntp + 1], al[kc], vh2, vh3);
            }
        }
    }

    // ---- epilogue ----
    const float inv0 = 1.f / l0, inv1 = 1.f / l1;
#pragma unroll
    for (int nt = 0; nt < 8; ++nt) {
        const int c = nt * 8 + (lane & 3) * 2;
        if (gi0 < L) {
            float2 r = make_float2(o[nt][0] * inv0, o[nt][1] * inv0);
            *reinterpret_cast<float2*>(yb + (size_t)gi0 * D + c) = r;
        }
        if (gi1 < L) {
            float2 r = make_float2(o[nt][2] * inv1, o[nt][3] * inv1);
            *reinterpret_cast<float2*>(yb + (size_t)gi1 * D + c) = r;
        }
    }
}

extern "C" void kernel_launch(void* const* d_in, const int* in_sizes, int n_in,
                              void* d_out, int out_size)
{
    const float* samples = (const float*)d_in[0];   // [B, L, D] fp32
    const float* weights = (const float*)d_in[1];   // [2, H, 6] fp32
    float* out = (float*)d_out;                     // [B, L, D] fp32

    float* scratch = nullptr;
    cudaGetSymbolAddress((void**)&scratch, g_x1);

    dim3 grid(NT, B * H);   // 16 x 128
    encoder_layer_tc<<<grid, 128>>>(samples, weights, scratch);
    encoder_layer_tc<<<grid, 128>>>(scratch, weights + H * 6, out);
}

// round 3
// speedup vs baseline: 3.1069x; 1.0000x over previous
#include <cuda_runtime.h>
#include <cuda_bf16.h>
#include <cmath>
#include <cstdint>

// Problem constants (fixed by setup_inputs: B=8, L=20*50+1, d_model=1024, H=16, 2 layers)
namespace {
constexpr int B    = 8;
constexpr int L    = 1001;
constexpr int D    = 1024;
constexpr int H    = 16;
constexpr int DK   = 64;
constexpr int NKQ  = 1000;   // query row index
constexpr int KCLS = 50;     // class block size
constexpr int TI   = 64;     // row tile (4 warps x 16)
constexpr int TJ   = 64;     // key tile
constexpr int NT   = (L + TJ - 1) / TJ;   // 16
constexpr int LDS  = 72;     // bf16 elems per smem row (stride 144B: conflict-free ldmatrix)
constexpr float SCALE = 0.125f;
}

// Layer-1 intermediate (32.8 MB) — __device__ global scratch (no-alloc rule).
__device__ float g_x1[(size_t)B * L * D];

__device__ __forceinline__ uint32_t smem_u32(const void* p) {
    return (uint32_t)__cvta_generic_to_shared(p);
}
__device__ __forceinline__ void ldmx4(uint32_t a, uint32_t& r0, uint32_t& r1, uint32_t& r2, uint32_t& r3) {
    asm volatile("ldmatrix.sync.aligned.m8n8.x4.shared.b16 {%0,%1,%2,%3},[%4];"
                 : "=r"(r0), "=r"(r1), "=r"(r2), "=r"(r3) : "r"(a));
}
__device__ __forceinline__ void ldmx4t(uint32_t a, uint32_t& r0, uint32_t& r1, uint32_t& r2, uint32_t& r3) {
    asm volatile("ldmatrix.sync.aligned.m8n8.x4.trans.shared.b16 {%0,%1,%2,%3},[%4];"
                 : "=r"(r0), "=r"(r1), "=r"(r2), "=r"(r3) : "r"(a));
}
__device__ __forceinline__ void mma_bf16(float* d, const uint32_t* a, uint32_t b0, uint32_t b1) {
    asm volatile("mma.sync.aligned.m16n8k16.row.col.f32.bf16.bf16.f32 "
                 "{%0,%1,%2,%3},{%4,%5,%6,%7},{%8,%9},{%0,%1,%2,%3};"
                 : "+f"(d[0]), "+f"(d[1]), "+f"(d[2]), "+f"(d[3])
                 : "r"(a[0]), "r"(a[1]), "r"(a[2]), "r"(a[3]), "r"(b0), "r"(b1));
}
__device__ __forceinline__ uint32_t pack_bf2(__nv_bfloat16 lo, __nv_bfloat16 hi) {
    __nv_bfloat162 t = __halves2bfloat162(lo, hi);   // lo -> .x (low half)
    return *reinterpret_cast<uint32_t*>(&t);
}
// split a,b into bf16 hi-pair and lo-pair (packed, low half = first arg)
__device__ __forceinline__ void split2(float a, float b, uint32_t& hi, uint32_t& lo) {
    __nv_bfloat16 ha = __float2bfloat16_rn(a), hb = __float2bfloat16_rn(b);
    float ra = a - __bfloat162float(ha);
    float rb = b - __bfloat162float(hb);
    hi = pack_bf2(ha, hb);
    lo = pack_bf2(__float2bfloat16_rn(ra), __float2bfloat16_rn(rb));
}

// Stage a 64x64 fp32 tile (rows base..base+63 of x-slice, cols = this head's dk)
// into bf16 hi/lo smem tiles, zero-filling out-of-range rows. 128 threads.
__device__ __forceinline__ void stage_tile(const float* __restrict__ src, int base_row,
                                           float scale, __nv_bfloat16* sH, __nv_bfloat16* sL,
                                           int tid) {
#pragma unroll
    for (int it = 0; it < 8; ++it) {
        int idx = tid + 128 * it;
        int row = idx >> 4, c4 = (idx & 15) * 4;
        int g = base_row + row;
        float4 v = make_float4(0.f, 0.f, 0.f, 0.f);
        if (g < L) v = *reinterpret_cast<const float4*>(src + (size_t)g * D + c4);
        v.x *= scale; v.y *= scale; v.z *= scale; v.w *= scale;
        uint32_t h0, l0, h1, l1;
        split2(v.x, v.y, h0, l0);
        split2(v.z, v.w, h1, l1);
        uint32_t* pH = reinterpret_cast<uint32_t*>(sH + row * LDS + c4);
        uint32_t* pL = reinterpret_cast<uint32_t*>(sL + row * LDS + c4);
        pH[0] = h0; pH[1] = h1;
        pL[0] = l0; pL[1] = l1;
    }
}

__device__ __forceinline__ float tmul(int gi, int ib, bool iq, int gj, const float* t6) {
    if (iq)        return (gj == NKQ) ? t6[5] : t6[4];
    if (gj == NKQ) return t6[3];
    if (gi == gj)  return t6[0];
    return (ib == gj / KCLS) ? t6[1] : t6[2];
}

__global__ void __launch_bounds__(128, 3)
encoder_layer_tc(const float* __restrict__ x,
                 const float* __restrict__ w6,   // [H][6] for this layer
                 float* __restrict__ y)
{
    __shared__ __nv_bfloat16 sKh[TJ * LDS];
    __shared__ __nv_bfloat16 sKl[TJ * LDS];

    const int tid  = threadIdx.x;
    const int w    = tid >> 5;
    const int lane = tid & 31;
    const int h    = blockIdx.y & (H - 1);
    const int b    = blockIdx.y >> 4;
    const int i_base = blockIdx.x * TI;

    const float* xb = x + (size_t)b * L * D + h * DK;
    float*       yb = y + (size_t)b * L * D + h * DK;

    float t6[6];
#pragma unroll
    for (int q = 0; q < 6; ++q) t6[q] = tanhf(w6[h * 6 + q]);

    // lane-derived ldmatrix offset pieces
    const int lrA = (lane & 7) + ((lane >> 3) & 1) * 8;  // A / trans-B row part
    const int lcA = ((lane >> 4) & 1) * 8;               // A / trans-B col part
    const int lrK = (lane & 7) + ((lane >> 4) & 1) * 8;  // non-trans B row part
    const int lcK = ((lane >> 3) & 1) * 8;               // non-trans B col part

    // ---- stage Q (pre-scaled), hoist A-fragments into registers ----
    stage_tile(xb, i_base, SCALE, sKh, sKl, tid);
    __syncthreads();
    uint32_t qh[4][4], ql[4][4];
#pragma unroll
    for (int kc = 0; kc < 4; ++kc) {
        const int off = (w * 16 + lrA) * LDS + kc * 16 + lcA;
        ldmx4(smem_u32(sKh + off), qh[kc][0], qh[kc][1], qh[kc][2], qh[kc][3]);
        ldmx4(smem_u32(sKl + off), ql[kc][0], ql[kc][1], ql[kc][2], ql[kc][3]);
    }

    float o[8][4];
#pragma unroll
    for (int nt = 0; nt < 8; ++nt)
#pragma unroll
        for (int v = 0; v < 4; ++v) o[nt][v] = 0.f;
    float m0 = -INFINITY, m1 = -INFINITY, l0 = 0.f, l1 = 0.f;

    const int gi0 = i_base + w * 16 + (lane >> 2);
    const int gi1 = gi0 + 8;
    const int ib0 = gi0 / KCLS, ib1 = gi1 / KCLS;
    const bool iq0 = (gi0 == NKQ), iq1 = (gi1 == NKQ);

    for (int jt = 0; jt < NT; ++jt) {
        const int j_base = jt * TJ;
        __syncthreads();                       // previous O-gemm reads done
        stage_tile(xb, j_base, 1.0f, sKh, sKl, tid);
        __syncthreads();

        // ---- S = Q K^T (bf16x3) ----
        float acc[8][4];
#pragma unroll
        for (int nt = 0; nt < 8; ++nt)
#pragma unroll
            for (int v = 0; v < 4; ++v) acc[nt][v] = 0.f;

#pragma unroll
        for (int kc = 0; kc < 4; ++kc) {
#pragma unroll
            for (int ntp = 0; ntp < 4; ++ntp) {
                const int off = (16 * ntp + lrK) * LDS + kc * 16 + lcK;
                uint32_t bh0, bh1, bh2, bh3, bl0, bl1, bl2, bl3;
                ldmx4(smem_u32(sKh + off), bh0, bh1, bh2, bh3);
                ldmx4(smem_u32(sKl + off), bl0, bl1, bl2, bl3);
                mma_bf16(acc[2 * ntp],     qh[kc], bh0, bh1);
                mma_bf16(acc[2 * ntp],     qh[kc], bl0, bl1);
                mma_bf16(acc[2 * ntp],     ql[kc], bh0, bh1);
                mma_bf16(acc[2 * ntp + 1], qh[kc], bh2, bh3);
                mma_bf16(acc[2 * ntp + 1], qh[kc], bl2, bl3);
                mma_bf16(acc[2 * ntp + 1], ql[kc], bh2, bh3);
            }
        }

        // ---- online softmax + structured multiplier, pack P as A-fragments ----
        float rm0 = -INFINITY, rm1 = -INFINITY;
#pragma unroll
        for (int nt = 0; nt < 8; ++nt) {
            rm0 = fmaxf(rm0, fmaxf(acc[nt][0], acc[nt][1]));
            rm1 = fmaxf(rm1, fmaxf(acc[nt][2], acc[nt][3]));
        }
        rm0 = fmaxf(rm0, __shfl_xor_sync(0xffffffffu, rm0, 1));
        rm0 = fmaxf(rm0, __shfl_xor_sync(0xffffffffu, rm0, 2));
        rm1 = fmaxf(rm1, __shfl_xor_sync(0xffffffffu, rm1, 1));
        rm1 = fmaxf(rm1, __shfl_xor_sync(0xffffffffu, rm1, 2));
        const float mn0 = fmaxf(m0, rm0), mn1 = fmaxf(m1, rm1);
        const float sc0 = __expf(m0 - mn0), sc1 = __expf(m1 - mn1);
        m0 = mn0; m1 = mn1;
        l0 *= sc0; l1 *= sc1;
#pragma unroll
        for (int nt = 0; nt < 8; ++nt) {
            o[nt][0] *= sc0; o[nt][1] *= sc0;
            o[nt][2] *= sc1; o[nt][3] *= sc1;
        }

        uint32_t ah[4][4], al[4][4];
        float ps0 = 0.f, ps1 = 0.f;
#pragma unroll
        for (int nt = 0; nt < 8; ++nt) {
            const int gj0 = j_base + nt * 8 + (lane & 3) * 2;
            const int gj1 = gj0 + 1;
            const float e00 = (gj0 < L) ? __expf(acc[nt][0] - mn0) : 0.f;
            const float e01 = (gj1 < L) ? __expf(acc[nt][1] - mn0) : 0.f;
            const float e10 = (gj0 < L) ? __expf(acc[nt][2] - mn1) : 0.f;
            const float e11 = (gj1 < L) ? __expf(acc[nt][3] - mn1) : 0.f;
            ps0 += e00 + e01;
            ps1 += e10 + e11;
            const float p00 = e00 * tmul(gi0, ib0, iq0, gj0, t6);
            const float p01 = e01 * tmul(gi0, ib0, iq0, gj1, t6);
            const float p10 = e10 * tmul(gi1, ib1, iq1, gj0, t6);
            const float p11 = e11 * tmul(gi1, ib1, iq1, gj1, t6);
            const int kc = nt >> 1, of = (nt & 1) * 2;
            split2(p00, p01, ah[kc][of],     al[kc][of]);
            split2(p10, p11, ah[kc][of + 1], al[kc][of + 1]);
        }
        ps0 += __shfl_xor_sync(0xffffffffu, ps0, 1);
        ps0 += __shfl_xor_sync(0xffffffffu, ps0, 2);
        ps1 += __shfl_xor_sync(0xffffffffu, ps1, 1);
        ps1 += __shfl_xor_sync(0xffffffffu, ps1, 2);
        l0 += ps0; l1 += ps1;

        // ---- O += P V (V tile == K tile data, trans ldmatrix) ----
#pragma unroll
        for (int kc = 0; kc < 4; ++kc) {
#pragma unroll
            for (int ntp = 0; ntp < 4; ++ntp) {
                const int off = (kc * 16 + lrA) * LDS + 16 * ntp + lcA;
                uint32_t vh0, vh1, vh2, vh3, vl0, vl1, vl2, vl3;
                ldmx4t(smem_u32(sKh + off), vh0, vh1, vh2, vh3);
                ldmx4t(smem_u32(sKl + off), vl0, vl1, vl2, vl3);
                mma_bf16(o[2 * ntp],     ah[kc], vh0, vh1);
                mma_bf16(o[2 * ntp],     ah[kc], vl0, vl1);
                mma_bf16(o[2 * ntp],     al[kc], vh0, vh1);
                mma_bf16(o[2 * ntp + 1], ah[kc], vh2, vh3);
                mma_bf16(o[2 * ntp + 1], ah[kc], vl2, vl3);
                mma_bf16(o[2 * ntp + 1], al[kc], vh2, vh3);
            }
        }
    }

    // ---- epilogue ----
    const float inv0 = 1.f / l0, inv1 = 1.f / l1;
#pragma unroll
    for (int nt = 0; nt < 8; ++nt) {
        const int c = nt * 8 + (lane & 3) * 2;
        if (gi0 < L) {
            float2 r = make_float2(o[nt][0] * inv0, o[nt][1] * inv0);
            *reinterpret_cast<float2*>(yb + (size_t)gi0 * D + c) = r;
        }
        if (gi1 < L) {
            float2 r = make_float2(o[nt][2] * inv1, o[nt][3] * inv1);
            *reinterpret_cast<float2*>(yb + (size_t)gi1 * D + c) = r;
        }
    }
}

extern "C" void kernel_launch(void* const* d_in, const int* in_sizes, int n_in,
                              void* d_out, int out_size)
{
    const float* samples = (const float*)d_in[0];   // [B, L, D] fp32
    const float* weights = (const float*)d_in[1];   // [2, H, 6] fp32
    float* out = (float*)d_out;                     // [B, L, D] fp32

    float* scratch = nullptr;
    cudaGetSymbolAddress((void**)&scratch, g_x1);

    dim3 grid(NT, B * H);   // 16 x 128
    encoder_layer_tc<<<grid, 128>>>(samples, weights, scratch);
    encoder_layer_tc<<<grid, 128>>>(scratch, weights + H * 6, out);
}

// round 4
// speedup vs baseline: 3.1073x; 1.0001x over previous
#include <cuda_runtime.h>
#include <cuda_bf16.h>
#include <cmath>
#include <cstdint>

// Problem constants (fixed by setup_inputs: B=8, L=20*50+1, d_model=1024, H=16, 2 layers)
namespace {
constexpr int B    = 8;
constexpr int L    = 1001;
constexpr int D    = 1024;
constexpr int H    = 16;
constexpr int DK   = 64;
constexpr int NKQ  = 1000;   // query row index
constexpr int KCLS = 50;     // class block size
constexpr int TI   = 64;     // row tile (4 warps x 16)
constexpr int TJ   = 64;     // key tile
constexpr int NT   = (L + TJ - 1) / TJ;   // 16
constexpr int LDS  = 72;     // bf16 elems per smem row (stride 144B: conflict-free ldmatrix)
constexpr float SCALE = 0.125f;
}

// Layer-1 intermediate (32.8 MB) — __device__ global scratch (no-alloc rule).
__device__ float g_x1[(size_t)B * L * D];

__device__ __forceinline__ uint32_t smem_u32(const void* p) {
    return (uint32_t)__cvta_generic_to_shared(p);
}
__device__ __forceinline__ void ldmx4(uint32_t a, uint32_t& r0, uint32_t& r1, uint32_t& r2, uint32_t& r3) {
    asm volatile("ldmatrix.sync.aligned.m8n8.x4.shared.b16 {%0,%1,%2,%3},[%4];"
                 : "=r"(r0), "=r"(r1), "=r"(r2), "=r"(r3) : "r"(a));
}
__device__ __forceinline__ void ldmx4t(uint32_t a, uint32_t& r0, uint32_t& r1, uint32_t& r2, uint32_t& r3) {
    asm volatile("ldmatrix.sync.aligned.m8n8.x4.trans.shared.b16 {%0,%1,%2,%3},[%4];"
                 : "=r"(r0), "=r"(r1), "=r"(r2), "=r"(r3) : "r"(a));
}
__device__ __forceinline__ void mma_bf16(float* d, const uint32_t* a, uint32_t b0, uint32_t b1) {
    asm volatile("mma.sync.aligned.m16n8k16.row.col.f32.bf16.bf16.f32 "
                 "{%0,%1,%2,%3},{%4,%5,%6,%7},{%8,%9},{%0,%1,%2,%3};"
                 : "+f"(d[0]), "+f"(d[1]), "+f"(d[2]), "+f"(d[3])
                 : "r"(a[0]), "r"(a[1]), "r"(a[2]), "r"(a[3]), "r"(b0), "r"(b1));
}
__device__ __forceinline__ uint32_t pack_bf2(__nv_bfloat16 lo, __nv_bfloat16 hi) {
    __nv_bfloat162 t = __halves2bfloat162(lo, hi);   // lo -> .x (low half)
    return *reinterpret_cast<uint32_t*>(&t);
}
// split a,b into bf16 hi-pair and lo-pair (packed, low half = first arg)
__device__ __forceinline__ void split2(float a, float b, uint32_t& hi, uint32_t& lo) {
    __nv_bfloat16 ha = __float2bfloat16_rn(a), hb = __float2bfloat16_rn(b);
    float ra = a - __bfloat162float(ha);
    float rb = b - __bfloat162float(hb);
    hi = pack_bf2(ha, hb);
    lo = pack_bf2(__float2bfloat16_rn(ra), __float2bfloat16_rn(rb));
}

// Stage a 64x64 fp32 tile (rows base..base+63 of x-slice, cols = this head's dk)
// into bf16 hi/lo smem tiles, zero-filling out-of-range rows. 128 threads.
__device__ __forceinline__ void stage_tile(const float* __restrict__ src, int base_row,
                                           float scale, __nv_bfloat16* sH, __nv_bfloat16* sL,
                                           int tid) {
#pragma unroll
    for (int it = 0; it < 8; ++it) {
        int idx = tid + 128 * it;
        int row = idx >> 4, c4 = (idx & 15) * 4;
        int g = base_row + row;
        float4 v = make_float4(0.f, 0.f, 0.f, 0.f);
        if (g < L) v = *reinterpret_cast<const float4*>(src + (size_t)g * D + c4);
        v.x *= scale; v.y *= scale; v.z *= scale; v.w *= scale;
        uint32_t h0, l0, h1, l1;
        split2(v.x, v.y, h0, l0);
        split2(v.z, v.w, h1, l1);
        uint32_t* pH = reinterpret_cast<uint32_t*>(sH + row * LDS + c4);
        uint32_t* pL = reinterpret_cast<uint32_t*>(sL + row * LDS + c4);
        pH[0] = h0; pH[1] = h1;
        pL[0] = l0; pL[1] = l1;
    }
}

__device__ __forceinline__ float tmul(int gi, int ib, bool iq, int gj, const float* t6) {
    if (iq)        return (gj == NKQ) ? t6[5] : t6[4];
    if (gj == NKQ) return t6[3];
    if (gi == gj)  return t6[0];
    return (ib == gj / KCLS) ? t6[1] : t6[2];
}

__global__ void __launch_bounds__(128, 3)
encoder_layer_tc(const float* __restrict__ x,
                 const float* __restrict__ w6,   // [H][6] for this layer
                 float* __restrict__ y)
{
    __shared__ __nv_bfloat16 sKh[TJ * LDS];
    __shared__ __nv_bfloat16 sKl[TJ * LDS];

    const int tid  = threadIdx.x;
    const int w    = tid >> 5;
    const int lane = tid & 31;
    const int h    = blockIdx.y & (H - 1);
    const int b    = blockIdx.y >> 4;
    const int i_base = blockIdx.x * TI;

    const float* xb = x + (size_t)b * L * D + h * DK;
    float*       yb = y + (size_t)b * L * D + h * DK;

    float t6[6];
#pragma unroll
    for (int q = 0; q < 6; ++q) t6[q] = tanhf(w6[h * 6 + q]);

    // lane-derived ldmatrix offset pieces
    const int lrA = (lane & 7) + ((lane >> 3) & 1) * 8;  // A / trans-B row part
    const int lcA = ((lane >> 4) & 1) * 8;               // A / trans-B col part
    const int lrK = (lane & 7) + ((lane >> 4) & 1) * 8;  // non-trans B row part
    const int lcK = ((lane >> 3) & 1) * 8;               // non-trans B col part

    // ---- stage Q (pre-scaled), hoist A-fragments into registers ----
    stage_tile(xb, i_base, SCALE, sKh, sKl, tid);
    __syncthreads();
    uint32_t qh[4][4], ql[4][4];
#pragma unroll
    for (int kc = 0; kc < 4; ++kc) {
        const int off = (w * 16 + lrA) * LDS + kc * 16 + lcA;
        ldmx4(smem_u32(sKh + off), qh[kc][0], qh[kc][1], qh[kc][2], qh[kc][3]);
        ldmx4(smem_u32(sKl + off), ql[kc][0], ql[kc][1], ql[kc][2], ql[kc][3]);
    }

    float o[8][4];
#pragma unroll
    for (int nt = 0; nt < 8; ++nt)
#pragma unroll
        for (int v = 0; v < 4; ++v) o[nt][v] = 0.f;
    float m0 = -INFINITY, m1 = -INFINITY, l0 = 0.f, l1 = 0.f;

    const int gi0 = i_base + w * 16 + (lane >> 2);
    const int gi1 = gi0 + 8;
    const int ib0 = gi0 / KCLS, ib1 = gi1 / KCLS;
    const bool iq0 = (gi0 == NKQ), iq1 = (gi1 == NKQ);

    for (int jt = 0; jt < NT; ++jt) {
        const int j_base = jt * TJ;
        __syncthreads();                       // previous O-gemm reads done
        stage_tile(xb, j_base, 1.0f, sKh, sKl, tid);
        __syncthreads();

        // ---- S = Q K^T (bf16x3) ----
        float acc[8][4];
#pragma unroll
        for (int nt = 0; nt < 8; ++nt)
#pragma unroll
            for (int v = 0; v < 4; ++v) acc[nt][v] = 0.f;

#pragma unroll
        for (int kc = 0; kc < 4; ++kc) {
#pragma unroll
            for (int ntp = 0; ntp < 4; ++ntp) {
                const int off = (16 * ntp + lrK) * LDS + kc * 16 + lcK;
                uint32_t bh0, bh1, bh2, bh3, bl0, bl1, bl2, bl3;
                ldmx4(smem_u32(sKh + off), bh0, bh1, bh2, bh3);
                ldmx4(smem_u32(sKl + off), bl0, bl1, bl2, bl3);
                mma_bf16(acc[2 * ntp],     qh[kc], bh0, bh1);
                mma_bf16(acc[2 * ntp],     qh[kc], bl0, bl1);
                mma_bf16(acc[2 * ntp],     ql[kc], bh0, bh1);
                mma_bf16(acc[2 * ntp + 1], qh[kc], bh2, bh3);
                mma_bf16(acc[2 * ntp + 1], qh[kc], bl2, bl3);
                mma_bf16(acc[2 * ntp + 1], ql[kc], bh2, bh3);
            }
        }

        // ---- online softmax + structured multiplier, pack P as A-fragments ----
        float rm0 = -INFINITY, rm1 = -INFINITY;
#pragma unroll
        for (int nt = 0; nt < 8; ++nt) {
            rm0 = fmaxf(rm0, fmaxf(acc[nt][0], acc[nt][1]));
            rm1 = fmaxf(rm1, fmaxf(acc[nt][2], acc[nt][3]));
        }
        rm0 = fmaxf(rm0, __shfl_xor_sync(0xffffffffu, rm0, 1));
        rm0 = fmaxf(rm0, __shfl_xor_sync(0xffffffffu, rm0, 2));
        rm1 = fmaxf(rm1, __shfl_xor_sync(0xffffffffu, rm1, 1));
        rm1 = fmaxf(rm1, __shfl_xor_sync(0xffffffffu, rm1, 2));
        const float mn0 = fmaxf(m0, rm0), mn1 = fmaxf(m1, rm1);
        const float sc0 = __expf(m0 - mn0), sc1 = __expf(m1 - mn1);
        m0 = mn0; m1 = mn1;
        l0 *= sc0; l1 *= sc1;
#pragma unroll
        for (int nt = 0; nt < 8; ++nt) {
            o[nt][0] *= sc0; o[nt][1] *= sc0;
            o[nt][2] *= sc1; o[nt][3] *= sc1;
        }

        uint32_t ah[4][4], al[4][4];
        float ps0 = 0.f, ps1 = 0.f;
#pragma unroll
        for (int nt = 0; nt < 8; ++nt) {
            const int gj0 = j_base + nt * 8 + (lane & 3) * 2;
            const int gj1 = gj0 + 1;
            const float e00 = (gj0 < L) ? __expf(acc[nt][0] - mn0) : 0.f;
            const float e01 = (gj1 < L) ? __expf(acc[nt][1] - mn0) : 0.f;
            const float e10 = (gj0 < L) ? __expf(acc[nt][2] - mn1) : 0.f;
            const float e11 = (gj1 < L) ? __expf(acc[nt][3] - mn1) : 0.f;
            ps0 += e00 + e01;
            ps1 += e10 + e11;
            const float p00 = e00 * tmul(gi0, ib0, iq0, gj0, t6);
            const float p01 = e01 * tmul(gi0, ib0, iq0, gj1, t6);
            const float p10 = e10 * tmul(gi1, ib1, iq1, gj0, t6);
            const float p11 = e11 * tmul(gi1, ib1, iq1, gj1, t6);
            const int kc = nt >> 1, of = (nt & 1) * 2;
            split2(p00, p01, ah[kc][of],     al[kc][of]);
            split2(p10, p11, ah[kc][of + 1], al[kc][of + 1]);
        }
        ps0 += __shfl_xor_sync(0xffffffffu, ps0, 1);
        ps0 += __shfl_xor_sync(0xffffffffu, ps0, 2);
        ps1 += __shfl_xor_sync(0xffffffffu, ps1, 1);
        ps1 += __shfl_xor_sync(0xffffffffu, ps1, 2);
        l0 += ps0; l1 += ps1;

        // ---- O += P V (V tile == K tile data, trans ldmatrix) ----
#pragma unroll
        for (int kc = 0; kc < 4; ++kc) {
#pragma unroll
            for (int ntp = 0; ntp < 4; ++ntp) {
                const int off = (kc * 16 + lrA) * LDS + 16 * ntp + lcA;
                uint32_t vh0, vh1, vh2, vh3, vl0, vl1, vl2, vl3;
                ldmx4t(smem_u32(sKh + off), vh0, vh1, vh2, vh3);
                ldmx4t(smem_u32(sKl + off), vl0, vl1, vl2, vl3);
                mma_bf16(o[2 * ntp],     ah[kc], vh0, vh1);
                mma_bf16(o[2 * ntp],     ah[kc], vl0, vl1);
                mma_bf16(o[2 * ntp],     al[kc], vh0, vh1);
                mma_bf16(o[2 * ntp + 1], ah[kc], vh2, vh3);
                mma_bf16(o[2 * ntp + 1], ah[kc], vl2, vl3);
                mma_bf16(o[2 * ntp + 1], al[kc], vh2, vh3);
            }
        }
    }

    // ---- epilogue ----
    const float inv0 = 1.f / l0, inv1 = 1.f / l1;
#pragma unroll
    for (int nt = 0; nt < 8; ++nt) {
        const int c = nt * 8 + (lane & 3) * 2;
        if (gi0 < L) {
            float2 r = make_float2(o[nt][0] * inv0, o[nt][1] * inv0);
            *reinterpret_cast<float2*>(yb + (size_t)gi0 * D + c) = r;
        }
        if (gi1 < L) {
            float2 r = make_float2(o[nt][2] * inv1, o[nt][3] * inv1);
            *reinterpret_cast<float2*>(yb + (size_t)gi1 * D + c) = r;
        }
    }
}

extern "C" void kernel_launch(void* const* d_in, const int* in_sizes, int n_in,
                              void* d_out, int out_size)
{
    const float* samples = (const float*)d_in[0];   // [B, L, D] fp32
    const float* weights = (const float*)d_in[1];   // [2, H, 6] fp32
    float* out = (float*)d_out;                     // [B, L, D] fp32

    float* scratch = nullptr;
    cudaGetSymbolAddress((void**)&scratch, g_x1);

    dim3 grid(NT, B * H);   // 16 x 128
    encoder_layer_tc<<<grid, 128>>>(samples, weights, scratch);
    encoder_layer_tc<<<grid, 128>>>(scratch, weights + H * 6, out);
}

// round 6
// speedup vs baseline: 3.6636x; 1.1790x over previous
#include <cuda_runtime.h>
#include <cuda_bf16.h>
#include <cmath>
#include <cstdint>

// Problem constants (fixed by setup_inputs: B=8, L=20*50+1, d_model=1024, H=16, 2 layers)
namespace {
constexpr int B    = 8;
constexpr int L    = 1001;
constexpr int D    = 1024;
constexpr int H    = 16;
constexpr int DK   = 64;
constexpr int NKQ  = 1000;   // query row index
constexpr int KCLS = 50;     // class block size
constexpr int TI   = 64;     // row tile (4 warps x 16)
constexpr int TJ   = 64;     // key tile
constexpr int NT   = (L + TJ - 1) / TJ;   // 16
constexpr int LDS  = 72;     // bf16 elems per smem row (144B stride: conflict-free ldmatrix)
constexpr int TILE = TJ * LDS;            // elems per hi (or lo) tile
// fixed-base softmax: e^(s/8 - 24) = 2^(acc*C1 + C0). Scores are bounded (|s|<~16,
// diag >= 0 so denominator never vanishes); the common e^-24 scale cancels in o/l.
constexpr float C1 = 0.125f * 1.4426950408889634f;
constexpr float C0 = -24.0f * 1.4426950408889634f;
}

// bf16 hi/lo split activations (global scratch; no-alloc rule).
__device__ __nv_bfloat16 g_xh[(size_t)B * L * D];
__device__ __nv_bfloat16 g_xl[(size_t)B * L * D];
__device__ __nv_bfloat16 g_yh[(size_t)B * L * D];
__device__ __nv_bfloat16 g_yl[(size_t)B * L * D];

__device__ __forceinline__ uint32_t smem_u32(const void* p) {
    return (uint32_t)__cvta_generic_to_shared(p);
}
__device__ __forceinline__ void ldmx4(uint32_t a, uint32_t& r0, uint32_t& r1, uint32_t& r2, uint32_t& r3) {
    asm volatile("ldmatrix.sync.aligned.m8n8.x4.shared.b16 {%0,%1,%2,%3},[%4];"
                 : "=r"(r0), "=r"(r1), "=r"(r2), "=r"(r3) : "r"(a));
}
__device__ __forceinline__ void ldmx4t(uint32_t a, uint32_t& r0, uint32_t& r1, uint32_t& r2, uint32_t& r3) {
    asm volatile("ldmatrix.sync.aligned.m8n8.x4.trans.shared.b16 {%0,%1,%2,%3},[%4];"
                 : "=r"(r0), "=r"(r1), "=r"(r2), "=r"(r3) : "r"(a));
}
__device__ __forceinline__ void mma_bf16(float* d, const uint32_t* a, uint32_t b0, uint32_t b1) {
    asm volatile("mma.sync.aligned.m16n8k16.row.col.f32.bf16.bf16.f32 "
                 "{%0,%1,%2,%3},{%4,%5,%6,%7},{%8,%9},{%0,%1,%2,%3};"
                 : "+f"(d[0]), "+f"(d[1]), "+f"(d[2]), "+f"(d[3])
                 : "r"(a[0]), "r"(a[1]), "r"(a[2]), "r"(a[3]), "r"(b0), "r"(b1));
}
__device__ __forceinline__ float ex2(float x) {
    float r; asm("ex2.approx.ftz.f32 %0,%1;" : "=f"(r) : "f"(x)); return r;
}
__device__ __forceinline__ uint32_t pack_bf2(__nv_bfloat16 lo, __nv_bfloat16 hi) {
    __nv_bfloat162 t = __halves2bfloat162(lo, hi);
    return *reinterpret_cast<uint32_t*>(&t);
}
__device__ __forceinline__ void split2(float a, float b, uint32_t& hi, uint32_t& lo) {
    __nv_bfloat16 ha = __float2bfloat16_rn(a), hb = __float2bfloat16_rn(b);
    float ra = a - __bfloat162float(ha);
    float rb = b - __bfloat162float(hb);
    hi = pack_bf2(ha, hb);
    lo = pack_bf2(__float2bfloat16_rn(ra), __float2bfloat16_rn(rb));
}
__device__ __forceinline__ void cp_commit() { asm volatile("cp.async.commit_group;"); }
template<int N> __device__ __forceinline__ void cp_wait() {
    asm volatile("cp.async.wait_group %0;" :: "n"(N));
}

// Async-stage a 64-row tile (this head's 64 bf16 cols) of hi+lo into smem buffer.
// 1024 16B chunks / 128 threads = 8 per thread. OOB rows zero-filled via src-size=0.
__device__ __forceinline__ void stage_async(const __nv_bfloat16* __restrict__ gh,
                                            const __nv_bfloat16* __restrict__ gl,
                                            int base_row, __nv_bfloat16* sbuf, int tid) {
#pragma unroll
    for (int it = 0; it < 8; ++it) {
        int idx = tid + 128 * it;          // 0..1023
        int arr = idx >> 9;                // 0 = hi, 1 = lo
        int rem = idx & 511;
        int row = rem >> 3;
        int ch  = rem & 7;                 // 16B chunk within 128B row segment
        int g   = base_row + row;
        const __nv_bfloat16* src = (arr ? gl : gh) + (size_t)g * D + ch * 8;
        uint32_t dst = smem_u32(sbuf + arr * TILE + row * LDS + ch * 8);
        int sz = (g < L) ? 16 : 0;
        asm volatile("cp.async.ca.shared.global [%0], [%1], 16, %2;"
                     :: "r"(dst), "l"(src), "r"(sz));
    }
}

__device__ __forceinline__ float tmul(int gi, int ib, bool iq, int gj, const float* t6) {
    if (iq)        return (gj == NKQ) ? t6[5] : t6[4];
    if (gj == NKQ) return t6[3];
    if (gi == gj)  return t6[0];
    return (ib == gj / KCLS) ? t6[1] : t6[2];
}

// Initial fp32 -> bf16 hi/lo split (one-time).
__global__ void convert_split(const float* __restrict__ x,
                              __nv_bfloat16* __restrict__ xh,
                              __nv_bfloat16* __restrict__ xl) {
    size_t i = ((size_t)blockIdx.x * blockDim.x + threadIdx.x) * 4;
    float4 v = *reinterpret_cast<const float4*>(x + i);
    uint32_t h0, l0, h1, l1;
    split2(v.x, v.y, h0, l0);
    split2(v.z, v.w, h1, l1);
    *reinterpret_cast<uint2*>(xh + i) = make_uint2(h0, h1);
    *reinterpret_cast<uint2*>(xl + i) = make_uint2(l0, l1);
}

template<bool SPLIT_OUT>
__global__ void __launch_bounds__(128, 3)
encoder_layer_tc(const __nv_bfloat16* __restrict__ xh,
                 const __nv_bfloat16* __restrict__ xl,
                 const float* __restrict__ w6,        // [H][6] for this layer
                 __nv_bfloat16* __restrict__ yh,      // SPLIT_OUT
                 __nv_bfloat16* __restrict__ yl,      // SPLIT_OUT
                 float* __restrict__ yo)              // !SPLIT_OUT
{
    __shared__ __nv_bfloat16 sb[2][2 * TILE];   // double-buffered hi+lo tiles (36.9 KB)

    const int tid  = threadIdx.x;
    const int w    = tid >> 5;
    const int lane = tid & 31;
    const int h    = blockIdx.y & (H - 1);
    const int b    = blockIdx.y >> 4;
    const int i_base = blockIdx.x * TI;

    const size_t slice = (size_t)b * L * D + h * DK;
    const __nv_bfloat16* xhb = xh + slice;
    const __nv_bfloat16* xlb = xl + slice;

    float t6[6];
#pragma unroll
    for (int q = 0; q < 6; ++q) t6[q] = tanhf(w6[h * 6 + q]);

    // lane-derived ldmatrix offset pieces
    const int lrA = (lane & 7) + ((lane >> 3) & 1) * 8;  // A / trans-B row part
    const int lcA = ((lane >> 4) & 1) * 8;               // A / trans-B col part
    const int lrK = (lane & 7) + ((lane >> 4) & 1) * 8;  // non-trans B row part
    const int lcK = ((lane >> 3) & 1) * 8;               // non-trans B col part

    // stage Q -> buf0, K(0) -> buf1 (both in flight)
    stage_async(xhb, xlb, i_base, sb[0], tid);
    cp_commit();
    stage_async(xhb, xlb, 0, sb[1], tid);
    cp_commit();
    cp_wait<1>();            // Q landed
    __syncthreads();

    // hoist Q A-fragments (unscaled; 1/8 folded into exp argument)
    uint32_t qh[4][4], ql[4][4];
#pragma unroll
    for (int kc = 0; kc < 4; ++kc) {
        const int off = (w * 16 + lrA) * LDS + kc * 16 + lcA;
        ldmx4(smem_u32(sb[0] + off),        qh[kc][0], qh[kc][1], qh[kc][2], qh[kc][3]);
        ldmx4(smem_u32(sb[0] + TILE + off), ql[kc][0], ql[kc][1], ql[kc][2], ql[kc][3]);
    }
    __syncthreads();         // all warps done reading buf0 before K(1) overwrites it

    float o[8][4];
#pragma unroll
    for (int nt = 0; nt < 8; ++nt)
#pragma unroll
        for (int v = 0; v < 4; ++v) o[nt][v] = 0.f;
    float l0 = 0.f, l1 = 0.f;

    const int gi0 = i_base + w * 16 + (lane >> 2);
    const int gi1 = gi0 + 8;
    const int ib0 = gi0 / KCLS, ib1 = gi1 / KCLS;
    const bool iq0 = (gi0 == NKQ), iq1 = (gi1 == NKQ);

    for (int jt = 0; jt < NT; ++jt) {
        const int j_base = jt * TJ;
        __nv_bfloat16* kb = sb[(jt + 1) & 1];   // K(jt) lives here

        if (jt + 1 < NT)
            stage_async(xhb, xlb, (jt + 1) * TJ, sb[jt & 1], tid);
        cp_commit();
        cp_wait<1>();        // K(jt) landed
        __syncthreads();

        // ---- S = Q K^T (bf16x3, unscaled) ----
        float acc[8][4];
#pragma unroll
        for (int nt = 0; nt < 8; ++nt)
#pragma unroll
            for (int v = 0; v < 4; ++v) acc[nt][v] = 0.f;

#pragma unroll
        for (int kc = 0; kc < 4; ++kc) {
#pragma unroll
            for (int ntp = 0; ntp < 4; ++ntp) {
                const int off = (16 * ntp + lrK) * LDS + kc * 16 + lcK;
                uint32_t bh0, bh1, bh2, bh3, bl0, bl1, bl2, bl3;
                ldmx4(smem_u32(kb + off),        bh0, bh1, bh2, bh3);
                ldmx4(smem_u32(kb + TILE + off), bl0, bl1, bl2, bl3);
                mma_bf16(acc[2 * ntp],     qh[kc], bh0, bh1);
                mma_bf16(acc[2 * ntp],     qh[kc], bl0, bl1);
                mma_bf16(acc[2 * ntp],     ql[kc], bh0, bh1);
                mma_bf16(acc[2 * ntp + 1], qh[kc], bh2, bh3);
                mma_bf16(acc[2 * ntp + 1], qh[kc], bl2, bl3);
                mma_bf16(acc[2 * ntp + 1], ql[kc], bh2, bh3);
            }
        }

        // ---- fixed-base softmax weights + structured multiplier, pack A-frags ----
        uint32_t ah[4][4], al[4][4];
#pragma unroll
        for (int nt = 0; nt < 8; ++nt) {
            const int gj0 = j_base + nt * 8 + (lane & 3) * 2;
            const int gj1 = gj0 + 1;
            const bool v0 = (gj0 < L), v1 = (gj1 < L);
            const float e00 = v0 ? ex2(fmaf(acc[nt][0], C1, C0)) : 0.f;
            const float e01 = v1 ? ex2(fmaf(acc[nt][1], C1, C0)) : 0.f;
            const float e10 = v0 ? ex2(fmaf(acc[nt][2], C1, C0)) : 0.f;
            const float e11 = v1 ? ex2(fmaf(acc[nt][3], C1, C0)) : 0.f;
            l0 += e00 + e01;
            l1 += e10 + e11;
            const float p00 = e00 * tmul(gi0, ib0, iq0, gj0, t6);
            const float p01 = e01 * tmul(gi0, ib0, iq0, gj1, t6);
            const float p10 = e10 * tmul(gi1, ib1, iq1, gj0, t6);
            const float p11 = e11 * tmul(gi1, ib1, iq1, gj1, t6);
            const int kc = nt >> 1, of = (nt & 1) * 2;
            split2(p00, p01, ah[kc][of],     al[kc][of]);
            split2(p10, p11, ah[kc][of + 1], al[kc][of + 1]);
        }

        // ---- O += P V (V tile == K tile data, trans ldmatrix) ----
#pragma unroll
        for (int kc = 0; kc < 4; ++kc) {
#pragma unroll
            for (int ntp = 0; ntp < 4; ++ntp) {
                const int off = (kc * 16 + lrA) * LDS + 16 * ntp + lcA;
                uint32_t vh0, vh1, vh2, vh3, vl0, vl1, vl2, vl3;
                ldmx4t(smem_u32(kb + off),        vh0, vh1, vh2, vh3);
                ldmx4t(smem_u32(kb + TILE + off), vl0, vl1, vl2, vl3);
                mma_bf16(o[2 * ntp],     ah[kc], vh0, vh1);
                mma_bf16(o[2 * ntp],     ah[kc], vl0, vl1);
                mma_bf16(o[2 * ntp],     al[kc], vh0, vh1);
                mma_bf16(o[2 * ntp + 1], ah[kc], vh2, vh3);
                mma_bf16(o[2 * ntp + 1], ah[kc], vl2, vl3);
                mma_bf16(o[2 * ntp + 1], al[kc], vh2, vh3);
            }
        }
        __syncthreads();     // kb reads done before next stage overwrites
    }

    // ---- epilogue: reduce denominators once, divide, write ----
    l0 += __shfl_xor_sync(0xffffffffu, l0, 1);
    l0 += __shfl_xor_sync(0xffffffffu, l0, 2);
    l1 += __shfl_xor_sync(0xffffffffu, l1, 1);
    l1 += __shfl_xor_sync(0xffffffffu, l1, 2);
    const float inv0 = 1.f / l0, inv1 = 1.f / l1;

#pragma unroll
    for (int nt = 0; nt < 8; ++nt) {
        const int c = nt * 8 + (lane & 3) * 2;
        if (SPLIT_OUT) {
            if (gi0 < L) {
                uint32_t hi, lo;
                split2(o[nt][0] * inv0, o[nt][1] * inv0, hi, lo);
                *reinterpret_cast<uint32_t*>(yh + slice + (size_t)gi0 * D + c) = hi;
                *reinterpret_cast<uint32_t*>(yl + slice + (size_t)gi0 * D + c) = lo;
            }
            if (gi1 < L) {
                uint32_t hi, lo;
                split2(o[nt][2] * inv1, o[nt][3] * inv1, hi, lo);
                *reinterpret_cast<uint32_t*>(yh + slice + (size_t)gi1 * D + c) = hi;
                *reinterpret_cast<uint32_t*>(yl + slice + (size_t)gi1 * D + c) = lo;
            }
        } else {
            if (gi0 < L)
                *reinterpret_cast<float2*>(yo + slice + (size_t)gi0 * D + c) =
                    make_float2(o[nt][0] * inv0, o[nt][1] * inv0);
            if (gi1 < L)
                *reinterpret_cast<float2*>(yo + slice + (size_t)gi1 * D + c) =
                    make_float2(o[nt][2] * inv1, o[nt][3] * inv1);
        }
    }
}

extern "C" void kernel_launch(void* const* d_in, const int* in_sizes, int n_in,
                              void* d_out, int out_size)
{
    const float* samples = (const float*)d_in[0];   // [B, L, D] fp32
    const float* weights = (const float*)d_in[1];   // [2, H, 6] fp32
    float* out = (float*)d_out;                     // [B, L, D] fp32

    __nv_bfloat16 *xh, *xl, *yh, *yl;
    cudaGetSymbolAddress((void**)&xh, g_xh);
    cudaGetSymbolAddress((void**)&xl, g_xl);
    cudaGetSymbolAddress((void**)&yh, g_yh);
    cudaGetSymbolAddress((void**)&yl, g_yl);

    const int total4 = B * L * D / 4;               // exactly divisible
    convert_split<<<total4 / 256, 256>>>(samples, xh, xl);

    dim3 grid(NT, B * H);                           // 16 x 128
    encoder_layer_tc<true ><<<grid, 128>>>(xh, xl, weights,          yh, yl, nullptr);
    encoder_layer_tc<false><<<grid, 128>>>(yh, yl, weights + H * 6, nullptr, nullptr, out);
}

// round 9
// speedup vs baseline: 4.1163x; 1.1235x over previous
#include <cuda_runtime.h>
#include <cuda_bf16.h>
#include <cmath>
#include <cstdint>

// Problem constants (fixed by setup_inputs: B=8, L=20*50+1, d_model=1024, H=16, 2 layers)
namespace {
constexpr int B    = 8;
constexpr int L    = 1001;
constexpr int D    = 1024;
constexpr int H    = 16;
constexpr int DK   = 64;
constexpr int NKQ  = 1000;   // query row index
constexpr int KCLS = 50;     // class block size
constexpr int TI   = 64;     // row tile (4 warps x 16)
constexpr int TJ   = 64;     // key tile
constexpr int NT   = (L + TJ - 1) / TJ;   // 16
constexpr int LDS  = 72;     // bf16 elems per smem row (144B stride: conflict-free ldmatrix)
constexpr int TILE = TJ * LDS;            // elems per hi (or lo) tile
// fixed-base softmax: e^(s/8 - 24) = 2^(acc*C1 + C0). Scores are bounded (|s|<~16,
// diag >= 0 so denominator never vanishes); the common e^-24 scale cancels in o/l.
constexpr float C1 = 0.125f * 1.4426950408889634f;
constexpr float C0 = -24.0f * 1.4426950408889634f;
}

// bf16 hi/lo split activations (global scratch; no-alloc rule).
__device__ __nv_bfloat16 g_xh[(size_t)B * L * D];
__device__ __nv_bfloat16 g_xl[(size_t)B * L * D];
__device__ __nv_bfloat16 g_yh[(size_t)B * L * D];
__device__ __nv_bfloat16 g_yl[(size_t)B * L * D];

__device__ __forceinline__ uint32_t smem_u32(const void* p) {
    return (uint32_t)__cvta_generic_to_shared(p);
}
__device__ __forceinline__ void ldmx4(uint32_t a, uint32_t& r0, uint32_t& r1, uint32_t& r2, uint32_t& r3) {
    asm volatile("ldmatrix.sync.aligned.m8n8.x4.shared.b16 {%0,%1,%2,%3},[%4];"
                 : "=r"(r0), "=r"(r1), "=r"(r2), "=r"(r3) : "r"(a));
}
__device__ __forceinline__ void ldmx4t(uint32_t a, uint32_t& r0, uint32_t& r1, uint32_t& r2, uint32_t& r3) {
    asm volatile("ldmatrix.sync.aligned.m8n8.x4.trans.shared.b16 {%0,%1,%2,%3},[%4];"
                 : "=r"(r0), "=r"(r1), "=r"(r2), "=r"(r3) : "r"(a));
}
__device__ __forceinline__ void mma_bf16(float* d, const uint32_t* a, uint32_t b0, uint32_t b1) {
    asm volatile("mma.sync.aligned.m16n8k16.row.col.f32.bf16.bf16.f32 "
                 "{%0,%1,%2,%3},{%4,%5,%6,%7},{%8,%9},{%0,%1,%2,%3};"
                 : "+f"(d[0]), "+f"(d[1]), "+f"(d[2]), "+f"(d[3])
                 : "r"(a[0]), "r"(a[1]), "r"(a[2]), "r"(a[3]), "r"(b0), "r"(b1));
}
__device__ __forceinline__ float ex2(float x) {
    float r; asm("ex2.approx.ftz.f32 %0,%1;" : "=f"(r) : "f"(x)); return r;
}
// Fast 2-term bf16 split of pair (a,b): a -> low halves, b -> high halves.
// One packed cvt for hi, reconstruct hi parts by bit ops, one packed cvt for lo.
__device__ __forceinline__ void split2(float a, float b, uint32_t& hi, uint32_t& lo) {
    uint32_t h;
    asm("cvt.rn.bf16x2.f32 %0, %1, %2;" : "=r"(h) : "f"(b), "f"(a));
    const float fa = __uint_as_float(h << 16);
    const float fb = __uint_as_float(h & 0xffff0000u);
    uint32_t l;
    asm("cvt.rn.bf16x2.f32 %0, %1, %2;" : "=r"(l) : "f"(b - fb), "f"(a - fa));
    hi = h; lo = l;
}
__device__ __forceinline__ void cp_commit() { asm volatile("cp.async.commit_group;"); }
template<int N> __device__ __forceinline__ void cp_wait() {
    asm volatile("cp.async.wait_group %0;" :: "n"(N));
}

// Async-stage a 64-row tile (this head's 64 bf16 cols) of hi+lo into smem buffer.
// 1024 16B chunks / 128 threads = 8 per thread. OOB rows zero-filled via src-size=0.
__device__ __forceinline__ void stage_async(const __nv_bfloat16* __restrict__ gh,
                                            const __nv_bfloat16* __restrict__ gl,
                                            int base_row, __nv_bfloat16* sbuf, int tid) {
#pragma unroll
    for (int it = 0; it < 8; ++it) {
        int idx = tid + 128 * it;          // 0..1023
        int arr = idx >> 9;                // 0 = hi, 1 = lo
        int rem = idx & 511;
        int row = rem >> 3;
        int ch  = rem & 7;                 // 16B chunk within 128B row segment
        int g   = base_row + row;
        const __nv_bfloat16* src = (arr ? gl : gh) + (size_t)g * D + ch * 8;
        uint32_t dst = smem_u32(sbuf + arr * TILE + row * LDS + ch * 8);
        int sz = (g < L) ? 16 : 0;
        asm volatile("cp.async.ca.shared.global [%0], [%1], 16, %2;"
                     :: "r"(dst), "l"(src), "r"(sz));
    }
}

// Softmax + structured multiplier + pack P into A-fragments.
// wr* = {w_in_class, w_out_class, w_diag, w_querycol} per owned row.
template<bool MASK>
__device__ __forceinline__ void softmax_pack(const float acc[8][4], int j_base,
                                             int gi0, int gi1, int jlo0, int jlo1,
                                             const float* wr0, const float* wr1,
                                             uint32_t ah[4][4], uint32_t al[4][4],
                                             float& l0, float& l1, int lane)
{
#pragma unroll
    for (int nt = 0; nt < 8; ++nt) {
        const int gj0 = j_base + nt * 8 + (lane & 3) * 2;
        const int gj1 = gj0 + 1;
        float e00 = ex2(fmaf(acc[nt][0], C1, C0));
        float e01 = ex2(fmaf(acc[nt][1], C1, C0));
        float e10 = ex2(fmaf(acc[nt][2], C1, C0));
        float e11 = ex2(fmaf(acc[nt][3], C1, C0));
        if (MASK) {
            if (gj0 >= L) { e00 = 0.f; e10 = 0.f; }
            if (gj1 >= L) { e01 = 0.f; e11 = 0.f; }
        }
        l0 += e00 + e01;
        l1 += e10 + e11;
        // structured multiplier: class-interval compare, diag / query-col overrides
        float t00 = ((unsigned)(gj0 - jlo0) < (unsigned)KCLS) ? wr0[0] : wr0[1];
        float t01 = ((unsigned)(gj1 - jlo0) < (unsigned)KCLS) ? wr0[0] : wr0[1];
        float t10 = ((unsigned)(gj0 - jlo1) < (unsigned)KCLS) ? wr1[0] : wr1[1];
        float t11 = ((unsigned)(gj1 - jlo1) < (unsigned)KCLS) ? wr1[0] : wr1[1];
        if (gj0 == gi0) t00 = wr0[2];
        if (gj1 == gi0) t01 = wr0[2];
        if (gj0 == gi1) t10 = wr1[2];
        if (gj1 == gi1) t11 = wr1[2];
        if (gj0 == NKQ) { t00 = wr0[3]; t10 = wr1[3]; }
        if (gj1 == NKQ) { t01 = wr0[3]; t11 = wr1[3]; }
        const int kc = nt >> 1, of = (nt & 1) * 2;
        split2(e00 * t00, e01 * t01, ah[kc][of],     al[kc][of]);
        split2(e10 * t10, e11 * t11, ah[kc][of + 1], al[kc][of + 1]);
    }
}

// Initial fp32 -> bf16 hi/lo split (one-time).
__global__ void convert_split(const float* __restrict__ x,
                              __nv_bfloat16* __restrict__ xh,
                              __nv_bfloat16* __restrict__ xl) {
    size_t i = ((size_t)blockIdx.x * blockDim.x + threadIdx.x) * 4;
    float4 v = *reinterpret_cast<const float4*>(x + i);
    uint32_t h0, l0, h1, l1;
    split2(v.x, v.y, h0, l0);
    split2(v.z, v.w, h1, l1);
    *reinterpret_cast<uint2*>(xh + i) = make_uint2(h0, h1);
    *reinterpret_cast<uint2*>(xl + i) = make_uint2(l0, l1);
}

template<bool SPLIT_OUT>
__global__ void __launch_bounds__(128, 3)
encoder_layer_tc(const __nv_bfloat16* __restrict__ xh,
                 const __nv_bfloat16* __restrict__ xl,
                 const float* __restrict__ w6,        // [H][6] for this layer
                 __nv_bfloat16* __restrict__ yh,      // SPLIT_OUT
                 __nv_bfloat16* __restrict__ yl,      // SPLIT_OUT
                 float* __restrict__ yo)              // !SPLIT_OUT
{
    __shared__ __nv_bfloat16 sb[2][2 * TILE];   // double-buffered hi+lo tiles (36.9 KB)

    const int tid  = threadIdx.x;
    const int w    = tid >> 5;
    const int lane = tid & 31;
    const int h    = blockIdx.y & (H - 1);
    const int b    = blockIdx.y >> 4;
    const int i_base = blockIdx.x * TI;

    const size_t slice = (size_t)b * L * D + h * DK;
    const __nv_bfloat16* xhb = xh + slice;
    const __nv_bfloat16* xlb = xl + slice;

    float t6[6];
#pragma unroll
    for (int q = 0; q < 6; ++q) t6[q] = tanhf(w6[h * 6 + q]);

    // lane-derived ldmatrix offset pieces
    const int lrA = (lane & 7) + ((lane >> 3) & 1) * 8;  // A / trans-B row part
    const int lcA = ((lane >> 4) & 1) * 8;               // A / trans-B col part
    const int lrK = (lane & 7) + ((lane >> 4) & 1) * 8;  // non-trans B row part
    const int lcK = ((lane >> 3) & 1) * 8;               // non-trans B col part

    // stage Q -> buf0, K(0) -> buf1 (both in flight)
    stage_async(xhb, xlb, i_base, sb[0], tid);
    cp_commit();
    stage_async(xhb, xlb, 0, sb[1], tid);
    cp_commit();
    cp_wait<1>();            // Q landed
    __syncthreads();

    // hoist Q A-fragments (unscaled; 1/8 folded into exp argument)
    uint32_t qh[4][4], ql[4][4];
#pragma unroll
    for (int kc = 0; kc < 4; ++kc) {
        const int off = (w * 16 + lrA) * LDS + kc * 16 + lcA;
        ldmx4(smem_u32(sb[0] + off),        qh[kc][0], qh[kc][1], qh[kc][2], qh[kc][3]);
        ldmx4(smem_u32(sb[0] + TILE + off), ql[kc][0], ql[kc][1], ql[kc][2], ql[kc][3]);
    }
    __syncthreads();         // all warps done reading buf0 before K(1) overwrites it

    float o[8][4];
#pragma unroll
    for (int nt = 0; nt < 8; ++nt)
#pragma unroll
        for (int v = 0; v < 4; ++v) o[nt][v] = 0.f;
    float l0 = 0.f, l1 = 0.f;

    const int gi0 = i_base + w * 16 + (lane >> 2);
    const int gi1 = gi0 + 8;
    const int jlo0 = (gi0 / KCLS) * KCLS;
    const int jlo1 = (gi1 / KCLS) * KCLS;
    // per-row weight quadruple {in_class, out_class, diag, query_col};
    // query row (gi==NKQ): everything t6[4] except col NKQ -> t6[5]
    float wr0[4], wr1[4];
    if (gi0 == NKQ) { wr0[0] = wr0[1] = t6[4]; wr0[2] = wr0[3] = t6[5]; }
    else            { wr0[0] = t6[1]; wr0[1] = t6[2]; wr0[2] = t6[0]; wr0[3] = t6[3]; }
    if (gi1 == NKQ) { wr1[0] = wr1[1] = t6[4]; wr1[2] = wr1[3] = t6[5]; }
    else            { wr1[0] = t6[1]; wr1[1] = t6[2]; wr1[2] = t6[0]; wr1[3] = t6[3]; }

    for (int jt = 0; jt < NT; ++jt) {
        const int j_base = jt * TJ;
        __nv_bfloat16* kb = sb[(jt + 1) & 1];   // K(jt) lives here

        if (jt + 1 < NT)
            stage_async(xhb, xlb, (jt + 1) * TJ, sb[jt & 1], tid);
        cp_commit();
        cp_wait<1>();        // K(jt) landed
        __syncthreads();

        // ---- S = Q K^T (bf16x3, unscaled) ----
        float acc[8][4];
#pragma unroll
        for (int nt = 0; nt < 8; ++nt)
#pragma unroll
            for (int v = 0; v < 4; ++v) acc[nt][v] = 0.f;

#pragma unroll
        for (int kc = 0; kc < 4; ++kc) {
#pragma unroll
            for (int ntp = 0; ntp < 4; ++ntp) {
                const int off = (16 * ntp + lrK) * LDS + kc * 16 + lcK;
                uint32_t bh0, bh1, bh2, bh3, bl0, bl1, bl2, bl3;
                ldmx4(smem_u32(kb + off),        bh0, bh1, bh2, bh3);
                ldmx4(smem_u32(kb + TILE + off), bl0, bl1, bl2, bl3);
                mma_bf16(acc[2 * ntp],     qh[kc], bh0, bh1);
                mma_bf16(acc[2 * ntp],     qh[kc], bl0, bl1);
                mma_bf16(acc[2 * ntp],     ql[kc], bh0, bh1);
                mma_bf16(acc[2 * ntp + 1], qh[kc], bh2, bh3);
                mma_bf16(acc[2 * ntp + 1], qh[kc], bl2, bl3);
                mma_bf16(acc[2 * ntp + 1], ql[kc], bh2, bh3);
            }
        }

        // ---- softmax + multiplier + pack (mask only needed on last tile) ----
        uint32_t ah[4][4], al[4][4];
        if (jt == NT - 1)
            softmax_pack<true >(acc, j_base, gi0, gi1, jlo0, jlo1, wr0, wr1, ah, al, l0, l1, lane);
        else
            softmax_pack<false>(acc, j_base, gi0, gi1, jlo0, jlo1, wr0, wr1, ah, al, l0, l1, lane);

        // ---- O += P V (V tile == K tile data, trans ldmatrix) ----
#pragma unroll
        for (int kc = 0; kc < 4; ++kc) {
#pragma unroll
            for (int ntp = 0; ntp < 4; ++ntp) {
                const int off = (kc * 16 + lrA) * LDS + 16 * ntp + lcA;
                uint32_t vh0, vh1, vh2, vh3, vl0, vl1, vl2, vl3;
                ldmx4t(smem_u32(kb + off),        vh0, vh1, vh2, vh3);
                ldmx4t(smem_u32(kb + TILE + off), vl0, vl1, vl2, vl3);
                mma_bf16(o[2 * ntp],     ah[kc], vh0, vh1);
                mma_bf16(o[2 * ntp],     ah[kc], vl0, vl1);
                mma_bf16(o[2 * ntp],     al[kc], vh0, vh1);
                mma_bf16(o[2 * ntp + 1], ah[kc], vh2, vh3);
                mma_bf16(o[2 * ntp + 1], ah[kc], vl2, vl3);
                mma_bf16(o[2 * ntp + 1], al[kc], vh2, vh3);
            }
        }
        __syncthreads();     // kb reads done before next stage overwrites
    }

    // ---- epilogue: reduce denominators once, divide, write ----
    l0 += __shfl_xor_sync(0xffffffffu, l0, 1);
    l0 += __shfl_xor_sync(0xffffffffu, l0, 2);
    l1 += __shfl_xor_sync(0xffffffffu, l1, 1);
    l1 += __shfl_xor_sync(0xffffffffu, l1, 2);
    const float inv0 = 1.f / l0, inv1 = 1.f / l1;

#pragma unroll
    for (int nt = 0; nt < 8; ++nt) {
        const int c = nt * 8 + (lane & 3) * 2;
        if (SPLIT_OUT) {
            if (gi0 < L) {
                uint32_t hi, lo;
                split2(o[nt][0] * inv0, o[nt][1] * inv0, hi, lo);
                *reinterpret_cast<uint32_t*>(yh + slice + (size_t)gi0 * D + c) = hi;
                *reinterpret_cast<uint32_t*>(yl + slice + (size_t)gi0 * D + c) = lo;
            }
            if (gi1 < L) {
                uint32_t hi, lo;
                split2(o[nt][2] * inv1, o[nt][3] * inv1, hi, lo);
                *reinterpret_cast<uint32_t*>(yh + slice + (size_t)gi1 * D + c) = hi;
                *reinterpret_cast<uint32_t*>(yl + slice + (size_t)gi1 * D + c) = lo;
            }
        } else {
            if (gi0 < L)
                *reinterpret_cast<float2*>(yo + slice + (size_t)gi0 * D + c) =
                    make_float2(o[nt][0] * inv0, o[nt][1] * inv0);
            if (gi1 < L)
                *reinterpret_cast<float2*>(yo + slice + (size_t)gi1 * D + c) =
                    make_float2(o[nt][2] * inv1, o[nt][3] * inv1);
        }
    }
}

extern "C" void kernel_launch(void* const* d_in, const int* in_sizes, int n_in,
                              void* d_out, int out_size)
{
    const float* samples = (const float*)d_in[0];   // [B, L, D] fp32
    const float* weights = (const float*)d_in[1];   // [2, H, 6] fp32
    float* out = (float*)d_out;                     // [B, L, D] fp32

    __nv_bfloat16 *xh, *xl, *yh, *yl;
    cudaGetSymbolAddress((void**)&xh, g_xh);
    cudaGetSymbolAddress((void**)&xl, g_xl);
    cudaGetSymbolAddress((void**)&yh, g_yh);
    cudaGetSymbolAddress((void**)&yl, g_yl);

    const int total4 = B * L * D / 4;               // exactly divisible
    convert_split<<<total4 / 256, 256>>>(samples, xh, xl);

    dim3 grid(NT, B * H);                           // 16 x 128
    encoder_layer_tc<true ><<<grid, 128>>>(xh, xl, weights,          yh, yl, nullptr);
    encoder_layer_tc<false><<<grid, 128>>>(yh, yl, weights + H * 6, nullptr, nullptr, out);
}